// round 1
// baseline (speedup 1.0000x reference)
#include <cuda_runtime.h>
#include <cuda_bf16.h>
#include <math.h>

// Problem constants
#define BATCH 4
#define SEQ 2048
#define EMB 768
#define NHEAD 12
#define HDIM 64
#define MROWS (BATCH * SEQ)       // 8192
#define NQKV (3 * EMB)            // 2304

// Scratch (allocation-free rule: __device__ globals)
__device__ float g_q[BATCH * NHEAD * SEQ * HDIM];     // [b,h,s,d]
__device__ float g_k[BATCH * NHEAD * SEQ * HDIM];
__device__ float g_v[BATCH * NHEAD * SEQ * HDIM];
__device__ float g_attn[MROWS * EMB];                 // [b*s, h*d] row-major

// ---------------------------------------------------------------------------
// Kernel 1: QKV GEMM  C[m, j] = sum_d x[m,d] * w_qkv[j,d] + b_qkv[j]
// scattered into g_q/g_k/g_v with [b,h,s,d] layout.
// Tiles: BM=64, BN=64, BK=16, 256 threads, 4x4 per thread.
// ---------------------------------------------------------------------------
#define BM 64
#define BN 64
#define BK 16

__global__ __launch_bounds__(256)
void qkv_gemm_kernel(const float* __restrict__ x,
                     const float* __restrict__ w,
                     const float* __restrict__ bias) {
    __shared__ float As[BK][BM];
    __shared__ float Bs[BK][BN];

    const int m0 = blockIdx.x * BM;
    const int n0 = blockIdx.y * BN;
    const int tid = threadIdx.x;
    const int tx = tid & 15;          // 0..15 -> 4 cols each
    const int ty = tid >> 4;          // 0..15 -> 4 rows each
    const int lr = tid >> 2;          // 0..63 loader row
    const int lc = (tid & 3) * 4;     // 0,4,8,12 loader col

    float acc[4][4];
    #pragma unroll
    for (int i = 0; i < 4; i++)
        #pragma unroll
        for (int j = 0; j < 4; j++) acc[i][j] = 0.f;

    for (int k0 = 0; k0 < EMB; k0 += BK) {
        float4 av = *(const float4*)(x + (m0 + lr) * EMB + k0 + lc);
        float4 bv = *(const float4*)(w + (n0 + lr) * EMB + k0 + lc);
        As[lc + 0][lr] = av.x; As[lc + 1][lr] = av.y;
        As[lc + 2][lr] = av.z; As[lc + 3][lr] = av.w;
        Bs[lc + 0][lr] = bv.x; Bs[lc + 1][lr] = bv.y;
        Bs[lc + 2][lr] = bv.z; Bs[lc + 3][lr] = bv.w;
        __syncthreads();

        #pragma unroll
        for (int kk = 0; kk < BK; kk++) {
            float4 a4 = *(const float4*)&As[kk][ty * 4];
            float4 b4 = *(const float4*)&Bs[kk][tx * 4];
            float a[4] = {a4.x, a4.y, a4.z, a4.w};
            float b[4] = {b4.x, b4.y, b4.z, b4.w};
            #pragma unroll
            for (int i = 0; i < 4; i++)
                #pragma unroll
                for (int j = 0; j < 4; j++)
                    acc[i][j] += a[i] * b[j];
        }
        __syncthreads();
    }

    // Epilogue: bias + scatter. Each 64-wide n-tile is exactly one head of one
    // of q/k/v (2304 = 36 * 64, head boundaries aligned to 64).
    #pragma unroll
    for (int i = 0; i < 4; i++) {
        const int m = m0 + ty * 4 + i;
        const int b_idx = m >> 11;     // /2048
        const int s = m & 2047;
        #pragma unroll
        for (int j = 0; j < 4; j++) {
            const int n = n0 + tx * 4 + j;
            const float c = acc[i][j] + bias[n];
            const int which = n / EMB;
            const int jj = n % EMB;
            const int h = jj >> 6;
            const int hd = jj & 63;
            float* dst = (which == 0) ? g_q : (which == 1) ? g_k : g_v;
            dst[(((b_idx * NHEAD + h) * SEQ) + s) * HDIM + hd] = c;
        }
    }
}

// ---------------------------------------------------------------------------
// Kernel 2: flash-style attention. One thread per query, 128 queries/block,
// K/V tiles of 64 rows staged in smem (32 KB). Online softmax with rare
// rescale branch. Writes [b,s, h*64+d] into g_attn.
// ---------------------------------------------------------------------------
__global__ __launch_bounds__(128)
void attn_kernel() {
    const int bh = blockIdx.y;                 // 0..47
    const int b = bh / NHEAD;
    const int h = bh % NHEAD;
    const int tid = threadIdx.x;               // 128
    const int q_idx = blockIdx.x * 128 + tid;
    const float scale = 0.125f;                // 1/sqrt(64)

    __shared__ float4 Ks[64 * 16];             // 64 rows x 64 floats
    __shared__ float4 Vs[64 * 16];

    // Load query into registers
    float qreg[64];
    {
        const float4* qp = (const float4*)(g_q + ((size_t)bh * SEQ + q_idx) * HDIM);
        #pragma unroll
        for (int d4 = 0; d4 < 16; d4++) {
            float4 v = qp[d4];
            qreg[4 * d4 + 0] = v.x; qreg[4 * d4 + 1] = v.y;
            qreg[4 * d4 + 2] = v.z; qreg[4 * d4 + 3] = v.w;
        }
    }

    float o[64];
    #pragma unroll
    for (int d = 0; d < 64; d++) o[d] = 0.f;
    float mmax = -1e30f;
    float lsum = 0.f;

    for (int k0 = 0; k0 < SEQ; k0 += 64) {
        const float4* kg = (const float4*)(g_k + ((size_t)bh * SEQ + k0) * HDIM);
        const float4* vg = (const float4*)(g_v + ((size_t)bh * SEQ + k0) * HDIM);
        #pragma unroll
        for (int i = 0; i < 8; i++) {
            Ks[tid + i * 128] = kg[tid + i * 128];
            Vs[tid + i * 128] = vg[tid + i * 128];
        }
        __syncthreads();

        for (int kk = 0; kk < 64; kk++) {
            const float4* krow = &Ks[kk * 16];
            float sp[4] = {0.f, 0.f, 0.f, 0.f};
            #pragma unroll
            for (int d4 = 0; d4 < 16; d4++) {
                float4 a = krow[d4];
                sp[d4 & 3] += qreg[4 * d4 + 0] * a.x + qreg[4 * d4 + 1] * a.y
                            + qreg[4 * d4 + 2] * a.z + qreg[4 * d4 + 3] * a.w;
            }
            const float s = ((sp[0] + sp[1]) + (sp[2] + sp[3])) * scale;

            const float4* vrow = &Vs[kk * 16];
            if (s <= mmax) {
                const float p = __expf(s - mmax);
                lsum += p;
                #pragma unroll
                for (int d4 = 0; d4 < 16; d4++) {
                    float4 v = vrow[d4];
                    o[4 * d4 + 0] += p * v.x; o[4 * d4 + 1] += p * v.y;
                    o[4 * d4 + 2] += p * v.z; o[4 * d4 + 3] += p * v.w;
                }
            } else {
                const float f = __expf(mmax - s);   // rescale; taken ~log(S) times
                lsum = lsum * f + 1.f;
                #pragma unroll
                for (int d4 = 0; d4 < 16; d4++) {
                    float4 v = vrow[d4];
                    o[4 * d4 + 0] = o[4 * d4 + 0] * f + v.x;
                    o[4 * d4 + 1] = o[4 * d4 + 1] * f + v.y;
                    o[4 * d4 + 2] = o[4 * d4 + 2] * f + v.z;
                    o[4 * d4 + 3] = o[4 * d4 + 3] * f + v.w;
                }
                mmax = s;
            }
        }
        __syncthreads();
    }

    const float inv = 1.f / lsum;
    float4* outp = (float4*)(g_attn + ((size_t)(b * SEQ + q_idx)) * EMB + h * HDIM);
    #pragma unroll
    for (int d4 = 0; d4 < 16; d4++) {
        float4 v;
        v.x = o[4 * d4 + 0] * inv; v.y = o[4 * d4 + 1] * inv;
        v.z = o[4 * d4 + 2] * inv; v.w = o[4 * d4 + 3] * inv;
        outp[d4] = v;
    }
}

// ---------------------------------------------------------------------------
// Kernel 3: proj GEMM  out[m,n] = sum_d g_attn[m,d] * w_proj[n,d] + b_proj[n]
// ---------------------------------------------------------------------------
__global__ __launch_bounds__(256)
void proj_gemm_kernel(const float* __restrict__ w,
                      const float* __restrict__ bias,
                      float* __restrict__ out) {
    __shared__ float As[BK][BM];
    __shared__ float Bs[BK][BN];

    const int m0 = blockIdx.x * BM;
    const int n0 = blockIdx.y * BN;
    const int tid = threadIdx.x;
    const int tx = tid & 15;
    const int ty = tid >> 4;
    const int lr = tid >> 2;
    const int lc = (tid & 3) * 4;

    float acc[4][4];
    #pragma unroll
    for (int i = 0; i < 4; i++)
        #pragma unroll
        for (int j = 0; j < 4; j++) acc[i][j] = 0.f;

    for (int k0 = 0; k0 < EMB; k0 += BK) {
        float4 av = *(const float4*)(g_attn + (m0 + lr) * EMB + k0 + lc);
        float4 bv = *(const float4*)(w + (n0 + lr) * EMB + k0 + lc);
        As[lc + 0][lr] = av.x; As[lc + 1][lr] = av.y;
        As[lc + 2][lr] = av.z; As[lc + 3][lr] = av.w;
        Bs[lc + 0][lr] = bv.x; Bs[lc + 1][lr] = bv.y;
        Bs[lc + 2][lr] = bv.z; Bs[lc + 3][lr] = bv.w;
        __syncthreads();

        #pragma unroll
        for (int kk = 0; kk < BK; kk++) {
            float4 a4 = *(const float4*)&As[kk][ty * 4];
            float4 b4 = *(const float4*)&Bs[kk][tx * 4];
            float a[4] = {a4.x, a4.y, a4.z, a4.w};
            float b[4] = {b4.x, b4.y, b4.z, b4.w};
            #pragma unroll
            for (int i = 0; i < 4; i++)
                #pragma unroll
                for (int j = 0; j < 4; j++)
                    acc[i][j] += a[i] * b[j];
        }
        __syncthreads();
    }

    #pragma unroll
    for (int i = 0; i < 4; i++) {
        const int m = m0 + ty * 4 + i;
        #pragma unroll
        for (int j = 0; j < 4; j++) {
            const int n = n0 + tx * 4 + j;
            out[(size_t)m * EMB + n] = acc[i][j] + bias[n];
        }
    }
}

// ---------------------------------------------------------------------------
extern "C" void kernel_launch(void* const* d_in, const int* in_sizes, int n_in,
                              void* d_out, int out_size) {
    const float* x      = (const float*)d_in[0];   // [4,2048,768]
    const float* w_qkv  = (const float*)d_in[1];   // [2304,768]
    const float* b_qkv  = (const float*)d_in[2];   // [2304]
    const float* w_proj = (const float*)d_in[3];   // [768,768]
    const float* b_proj = (const float*)d_in[4];   // [768]
    float* out = (float*)d_out;                    // [4,2048,768]

    {
        dim3 grid(MROWS / BM, NQKV / BN);          // 128 x 36
        qkv_gemm_kernel<<<grid, 256>>>(x, w_qkv, b_qkv);
    }
    {
        dim3 grid(SEQ / 128, BATCH * NHEAD);       // 16 x 48
        attn_kernel<<<grid, 128>>>();
    }
    {
        dim3 grid(MROWS / BM, EMB / BN);           // 128 x 12
        proj_gemm_kernel<<<grid, 256>>>(w_proj, b_proj, out);
    }
}

// round 4
// speedup vs baseline: 6.7881x; 6.7881x over previous
#include <cuda_runtime.h>
#include <cuda_fp16.h>
#include <math.h>
#include <string.h>

#define BATCH 4
#define SEQ 2048
#define EMB 768
#define NHEAD 12
#define HDIM 64
#define MROWS (BATCH * SEQ)       // 8192
#define NQKV (3 * EMB)            // 2304

// fp16 scratch (allocation-free rule: __device__ globals)
__device__ __half g_xh[MROWS * EMB];
__device__ __half g_wqkvh[NQKV * EMB];
__device__ __half g_wprojh[EMB * EMB];
__device__ __half g_qh[BATCH * NHEAD * SEQ * HDIM];   // [bh][s][d]
__device__ __half g_kh[BATCH * NHEAD * SEQ * HDIM];   // [bh][s][d]
__device__ __half g_vth[BATCH * NHEAD * HDIM * SEQ];  // [bh][d][s]  (transposed!)
__device__ __half g_attnh[MROWS * EMB];               // [b*s][h*64+d]

// ---------------------------------------------------------------------------
__device__ __forceinline__ unsigned pack2(float a, float b) {
    __half2 h = __floats2half2_rn(a, b);
    unsigned u;
    memcpy(&u, &h, 4);
    return u;
}

// ---------------------------------------------------------------------------
__global__ void f32_to_f16_kernel(const float* __restrict__ in,
                                  __half* __restrict__ out, int n2) {
    int i = blockIdx.x * blockDim.x + threadIdx.x;
    if (i < n2) {
        float2 v = ((const float2*)in)[i];
        ((__half2*)out)[i] = __floats2half2_rn(v.x, v.y);
    }
}

// ---------------------------------------------------------------------------
__device__ __forceinline__ void mma_16816(float* d, const unsigned* a,
                                          const unsigned* b) {
    asm volatile(
        "mma.sync.aligned.m16n8k16.row.col.f32.f16.f16.f32 "
        "{%0,%1,%2,%3}, {%4,%5,%6,%7}, {%8,%9}, {%0,%1,%2,%3};\n"
        : "+f"(d[0]), "+f"(d[1]), "+f"(d[2]), "+f"(d[3])
        : "r"(a[0]), "r"(a[1]), "r"(a[2]), "r"(a[3]), "r"(b[0]), "r"(b[1]));
}

// ---------------------------------------------------------------------------
// HMMA GEMM core: C[m][n] = sum_k A[m][k]*B[n][k].  64x64 tile, BK=32,
// 128 threads = 4 warps in 2x2, warp tile 32x32.
// Smem tiles padded to stride 40 halves (80 B) for conflict-free frag loads.
// ---------------------------------------------------------------------------
#define GSTRIDE 40

struct GemmAcc { float c[2][4][4]; };

__device__ __forceinline__ void gemm_f16_core(
    const __half* __restrict__ A, const __half* __restrict__ B,
    int m0, int n0, int K, GemmAcc& acc,
    __half* As, __half* Bs) {
    const int tid = threadIdx.x;
    const int lane = tid & 31;
    const int w = tid >> 5;
    const int wm = w >> 1, wn = w & 1;
    const int g = lane >> 2, q4 = lane & 3;

    #pragma unroll
    for (int i = 0; i < 2; i++)
        #pragma unroll
        for (int j = 0; j < 4; j++)
            #pragma unroll
            for (int e = 0; e < 4; e++) acc.c[i][j][e] = 0.f;

    const __half* Ag = A + (size_t)m0 * K;
    const __half* Bg = B + (size_t)n0 * K;

    for (int k0 = 0; k0 < K; k0 += 32) {
        #pragma unroll
        for (int it = 0; it < 2; it++) {
            int i = tid + it * 128;
            int r = i >> 2, cc = i & 3;
            *(int4*)&As[r * GSTRIDE + cc * 8] =
                *(const int4*)&Ag[(size_t)r * K + k0 + cc * 8];
            *(int4*)&Bs[r * GSTRIDE + cc * 8] =
                *(const int4*)&Bg[(size_t)r * K + k0 + cc * 8];
        }
        __syncthreads();

        #pragma unroll
        for (int kc = 0; kc < 2; kc++) {
            unsigned af[2][4];
            #pragma unroll
            for (int i = 0; i < 2; i++) {
                const __half* base = &As[(wm * 32 + i * 16) * GSTRIDE + kc * 16];
                af[i][0] = *(const unsigned*)&base[(g) * GSTRIDE + 2 * q4];
                af[i][1] = *(const unsigned*)&base[(g + 8) * GSTRIDE + 2 * q4];
                af[i][2] = *(const unsigned*)&base[(g) * GSTRIDE + 8 + 2 * q4];
                af[i][3] = *(const unsigned*)&base[(g + 8) * GSTRIDE + 8 + 2 * q4];
            }
            #pragma unroll
            for (int j = 0; j < 4; j++) {
                const __half* base = &Bs[(wn * 32 + j * 8 + g) * GSTRIDE + kc * 16];
                unsigned bf[2];
                bf[0] = *(const unsigned*)&base[2 * q4];
                bf[1] = *(const unsigned*)&base[8 + 2 * q4];
                #pragma unroll
                for (int i = 0; i < 2; i++)
                    mma_16816(acc.c[i][j], af[i], bf);
            }
        }
        __syncthreads();
    }
}

// ---------------------------------------------------------------------------
// Kernel: QKV GEMM + bias + scatter to q/k (row) and v (transposed)
// ---------------------------------------------------------------------------
__global__ __launch_bounds__(128)
void qkv_gemm_f16(const float* __restrict__ bias) {
    __shared__ __half As[64 * GSTRIDE];
    __shared__ __half Bs[64 * GSTRIDE];
    const int m0 = blockIdx.x * 64;
    const int n0 = blockIdx.y * 64;

    GemmAcc acc;
    gemm_f16_core(g_xh, g_wqkvh, m0, n0, EMB, acc, As, Bs);

    const int tid = threadIdx.x;
    const int lane = tid & 31;
    const int w = tid >> 5;
    const int wm = w >> 1, wn = w & 1;
    const int g = lane >> 2, q4 = lane & 3;

    const int which = n0 / EMB;          // 0=q 1=k 2=v, uniform per block
    const int h = (n0 % EMB) / 64;       // uniform per block

    #pragma unroll
    for (int i = 0; i < 2; i++) {
        #pragma unroll
        for (int j = 0; j < 4; j++) {
            const int d = wn * 32 + j * 8 + 2 * q4;     // 0..62 even
            const int n = n0 + d;
            const float b0 = bias[n], b1 = bias[n + 1];
            #pragma unroll
            for (int rr = 0; rr < 2; rr++) {
                const int m = m0 + wm * 32 + i * 16 + g + rr * 8;
                const int bidx = m >> 11;
                const int s = m & 2047;
                const int bh = bidx * NHEAD + h;
                const float v0 = acc.c[i][j][rr * 2 + 0] + b0;
                const float v1 = acc.c[i][j][rr * 2 + 1] + b1;
                if (which == 2) {
                    g_vth[((size_t)bh * 64 + d) * SEQ + s] = __float2half(v0);
                    g_vth[((size_t)bh * 64 + d + 1) * SEQ + s] = __float2half(v1);
                } else {
                    __half* dst = (which == 0) ? g_qh : g_kh;
                    *(__half2*)&dst[((size_t)bh * SEQ + s) * 64 + d] =
                        __floats2half2_rn(v0, v1);
                }
            }
        }
    }
}

// ---------------------------------------------------------------------------
// Kernel: proj GEMM + bias -> fp32 out
// ---------------------------------------------------------------------------
__global__ __launch_bounds__(128)
void proj_gemm_f16(const float* __restrict__ bias, float* __restrict__ out) {
    __shared__ __half As[64 * GSTRIDE];
    __shared__ __half Bs[64 * GSTRIDE];
    const int m0 = blockIdx.x * 64;
    const int n0 = blockIdx.y * 64;

    GemmAcc acc;
    gemm_f16_core(g_attnh, g_wprojh, m0, n0, EMB, acc, As, Bs);

    const int tid = threadIdx.x;
    const int lane = tid & 31;
    const int w = tid >> 5;
    const int wm = w >> 1, wn = w & 1;
    const int g = lane >> 2, q4 = lane & 3;

    #pragma unroll
    for (int i = 0; i < 2; i++) {
        #pragma unroll
        for (int j = 0; j < 4; j++) {
            const int n = n0 + wn * 32 + j * 8 + 2 * q4;
            const float b0 = bias[n], b1 = bias[n + 1];
            #pragma unroll
            for (int rr = 0; rr < 2; rr++) {
                const int m = m0 + wm * 32 + i * 16 + g + rr * 8;
                float2 v;
                v.x = acc.c[i][j][rr * 2 + 0] + b0;
                v.y = acc.c[i][j][rr * 2 + 1] + b1;
                *(float2*)&out[(size_t)m * EMB + n] = v;
            }
        }
    }
}

// ---------------------------------------------------------------------------
// Kernel: flash attention with HMMA. Block = 64 queries (4 warps x 16),
// KV tiles of 64 keys. Smem K [key][d], Vt [d][key], stride 72 halves.
// ---------------------------------------------------------------------------
#define ASTRIDE 72

__global__ __launch_bounds__(128)
void attn_mma_kernel() {
    const int bh = blockIdx.y;                 // 0..47
    const int b = bh / NHEAD;
    const int h = bh % NHEAD;
    const int tid = threadIdx.x;
    const int lane = tid & 31;
    const int w = tid >> 5;
    const int g = lane >> 2, q4 = lane & 3;
    const int qbase = blockIdx.x * 64 + w * 16;

    __shared__ __half Ks[64 * ASTRIDE];
    __shared__ __half Vs[64 * ASTRIDE];

    // Q fragments (A-layout), loaded straight from gmem
    unsigned qa[4][4];
    {
        const __half* qp = g_qh + ((size_t)bh * SEQ + qbase) * HDIM;
        #pragma unroll
        for (int c = 0; c < 4; c++) {
            qa[c][0] = *(const unsigned*)&qp[(size_t)(g) * 64 + 16 * c + 2 * q4];
            qa[c][1] = *(const unsigned*)&qp[(size_t)(g + 8) * 64 + 16 * c + 2 * q4];
            qa[c][2] = *(const unsigned*)&qp[(size_t)(g) * 64 + 16 * c + 8 + 2 * q4];
            qa[c][3] = *(const unsigned*)&qp[(size_t)(g + 8) * 64 + 16 * c + 8 + 2 * q4];
        }
    }

    float O[8][4];
    #pragma unroll
    for (int n = 0; n < 8; n++)
        #pragma unroll
        for (int e = 0; e < 4; e++) O[n][e] = 0.f;
    float mA = -1e30f, mB = -1e30f, lA = 0.f, lB = 0.f;

    for (int k0 = 0; k0 < SEQ; k0 += 64) {
        // stage K tile [key][d] and Vt tile [d][key]
        const __half* kg = g_kh + ((size_t)bh * SEQ + k0) * HDIM;
        #pragma unroll
        for (int it = 0; it < 4; it++) {
            int i = tid + it * 128;
            int r = i >> 3, cc = i & 7;
            *(int4*)&Ks[r * ASTRIDE + cc * 8] =
                *(const int4*)&kg[(size_t)r * 64 + cc * 8];
            *(int4*)&Vs[r * ASTRIDE + cc * 8] =
                *(const int4*)&g_vth[((size_t)bh * 64 + r) * SEQ + k0 + cc * 8];
        }
        __syncthreads();

        // scores S = Q K^T * scale (fp32)
        float S[8][4];
        #pragma unroll
        for (int n = 0; n < 8; n++) {
            #pragma unroll
            for (int e = 0; e < 4; e++) S[n][e] = 0.f;
            #pragma unroll
            for (int c = 0; c < 4; c++) {
                const __half* base = &Ks[(n * 8 + g) * ASTRIDE + 16 * c];
                unsigned bf[2];
                bf[0] = *(const unsigned*)&base[2 * q4];
                bf[1] = *(const unsigned*)&base[8 + 2 * q4];
                mma_16816(S[n], qa[c], bf);
            }
            #pragma unroll
            for (int e = 0; e < 4; e++) S[n][e] *= 0.125f;
        }

        // online softmax (rows g and g+8 per thread; quads share a row)
        float tmA = -1e30f, tmB = -1e30f;
        #pragma unroll
        for (int n = 0; n < 8; n++) {
            tmA = fmaxf(tmA, fmaxf(S[n][0], S[n][1]));
            tmB = fmaxf(tmB, fmaxf(S[n][2], S[n][3]));
        }
        tmA = fmaxf(tmA, __shfl_xor_sync(0xffffffffu, tmA, 1));
        tmA = fmaxf(tmA, __shfl_xor_sync(0xffffffffu, tmA, 2));
        tmB = fmaxf(tmB, __shfl_xor_sync(0xffffffffu, tmB, 1));
        tmB = fmaxf(tmB, __shfl_xor_sync(0xffffffffu, tmB, 2));

        const float nmA = fmaxf(mA, tmA), nmB = fmaxf(mB, tmB);
        const float efA = __expf(mA - nmA), efB = __expf(mB - nmB);

        float sA = 0.f, sB = 0.f;
        #pragma unroll
        for (int n = 0; n < 8; n++) {
            S[n][0] = __expf(S[n][0] - nmA);
            S[n][1] = __expf(S[n][1] - nmA);
            S[n][2] = __expf(S[n][2] - nmB);
            S[n][3] = __expf(S[n][3] - nmB);
            sA += S[n][0] + S[n][1];
            sB += S[n][2] + S[n][3];
        }
        sA += __shfl_xor_sync(0xffffffffu, sA, 1);
        sA += __shfl_xor_sync(0xffffffffu, sA, 2);
        sB += __shfl_xor_sync(0xffffffffu, sB, 1);
        sB += __shfl_xor_sync(0xffffffffu, sB, 2);

        lA = lA * efA + sA;
        lB = lB * efB + sB;
        mA = nmA;
        mB = nmB;
        #pragma unroll
        for (int n = 0; n < 8; n++) {
            O[n][0] *= efA; O[n][1] *= efA;
            O[n][2] *= efB; O[n][3] *= efB;
        }

        // pack P (C-frag pairs -> A-frags)
        unsigned pa[4][4];
        #pragma unroll
        for (int c = 0; c < 4; c++) {
            pa[c][0] = pack2(S[2 * c][0], S[2 * c][1]);
            pa[c][1] = pack2(S[2 * c][2], S[2 * c][3]);
            pa[c][2] = pack2(S[2 * c + 1][0], S[2 * c + 1][1]);
            pa[c][3] = pack2(S[2 * c + 1][2], S[2 * c + 1][3]);
        }

        // O += P @ V   (B = Vt[d][key])
        #pragma unroll
        for (int n = 0; n < 8; n++) {
            #pragma unroll
            for (int c = 0; c < 4; c++) {
                const __half* base = &Vs[(n * 8 + g) * ASTRIDE + 16 * c];
                unsigned bf[2];
                bf[0] = *(const unsigned*)&base[2 * q4];
                bf[1] = *(const unsigned*)&base[8 + 2 * q4];
                mma_16816(O[n], pa[c], bf);
            }
        }
        __syncthreads();
    }

    // epilogue: normalize + store to g_attnh [b*s][h*64+d]
    const float rA = 1.f / lA, rB = 1.f / lB;
    #pragma unroll
    for (int n = 0; n < 8; n++) {
        const int d = n * 8 + 2 * q4;
        {
            const int q = qbase + g;
            *(__half2*)&g_attnh[((size_t)(b * SEQ + q)) * EMB + h * 64 + d] =
                __floats2half2_rn(O[n][0] * rA, O[n][1] * rA);
        }
        {
            const int q = qbase + g + 8;
            *(__half2*)&g_attnh[((size_t)(b * SEQ + q)) * EMB + h * 64 + d] =
                __floats2half2_rn(O[n][2] * rB, O[n][3] * rB);
        }
    }
}

// ---------------------------------------------------------------------------
extern "C" void kernel_launch(void* const* d_in, const int* in_sizes, int n_in,
                              void* d_out, int out_size) {
    const float* x      = (const float*)d_in[0];   // [4,2048,768]
    const float* w_qkv  = (const float*)d_in[1];   // [2304,768]
    const float* b_qkv  = (const float*)d_in[2];   // [2304]
    const float* w_proj = (const float*)d_in[3];   // [768,768]
    const float* b_proj = (const float*)d_in[4];   // [768]
    float* out = (float*)d_out;                    // [4,2048,768]

    __half* p_xh;     cudaGetSymbolAddress((void**)&p_xh, g_xh);
    __half* p_wqkvh;  cudaGetSymbolAddress((void**)&p_wqkvh, g_wqkvh);
    __half* p_wprojh; cudaGetSymbolAddress((void**)&p_wprojh, g_wprojh);

    {
        int n2 = MROWS * EMB / 2;
        f32_to_f16_kernel<<<(n2 + 255) / 256, 256>>>(x, p_xh, n2);
        n2 = NQKV * EMB / 2;
        f32_to_f16_kernel<<<(n2 + 255) / 256, 256>>>(w_qkv, p_wqkvh, n2);
        n2 = EMB * EMB / 2;
        f32_to_f16_kernel<<<(n2 + 255) / 256, 256>>>(w_proj, p_wprojh, n2);
    }
    {
        dim3 grid(MROWS / 64, NQKV / 64);          // 128 x 36
        qkv_gemm_f16<<<grid, 128>>>(b_qkv);
    }
    {
        dim3 grid(SEQ / 64, BATCH * NHEAD);        // 32 x 48
        attn_mma_kernel<<<grid, 128>>>();
    }
    {
        dim3 grid(MROWS / 64, EMB / 64);           // 128 x 12
        proj_gemm_f16<<<grid, 128>>>(b_proj, out);
    }
}

// round 5
// speedup vs baseline: 8.6983x; 1.2814x over previous
#include <cuda_runtime.h>
#include <cuda_fp16.h>
#include <math.h>
#include <string.h>

#define BATCH 4
#define SEQ 2048
#define EMB 768
#define NHEAD 12
#define HDIM 64
#define MROWS (BATCH * SEQ)       // 8192
#define NQKV (3 * EMB)            // 2304

// fp16 scratch (allocation-free rule: __device__ globals)
__device__ __half g_xh[MROWS * EMB];
__device__ __half g_wqkvh[NQKV * EMB];
__device__ __half g_wprojh[EMB * EMB];
__device__ __half g_qh[BATCH * NHEAD * SEQ * HDIM];   // [bh][s][d]
__device__ __half g_kh[BATCH * NHEAD * SEQ * HDIM];   // [bh][s][d]
__device__ __half g_vth[BATCH * NHEAD * HDIM * SEQ];  // [bh][d][s]  (transposed!)
__device__ __half g_attnh[MROWS * EMB];               // [b*s][h*64+d]

// ---------------------------------------------------------------------------
__device__ __forceinline__ unsigned pack2(float a, float b) {
    __half2 h = __floats2half2_rn(a, b);
    unsigned u;
    memcpy(&u, &h, 4);
    return u;
}

__device__ __forceinline__ unsigned smem_u32(const void* p) {
    return (unsigned)__cvta_generic_to_shared(p);
}

#define CP_ASYNC16(dst_u32, src_ptr) \
    asm volatile("cp.async.cg.shared.global [%0], [%1], 16;\n" \
                 :: "r"(dst_u32), "l"(src_ptr))
#define CP_COMMIT() asm volatile("cp.async.commit_group;\n")
#define CP_WAIT0()  asm volatile("cp.async.wait_group 0;\n" ::: "memory")

__device__ __forceinline__ void ldmatrix_x4(unsigned* r, unsigned addr) {
    asm volatile(
        "ldmatrix.sync.aligned.m8n8.x4.shared.b16 {%0,%1,%2,%3}, [%4];\n"
        : "=r"(r[0]), "=r"(r[1]), "=r"(r[2]), "=r"(r[3])
        : "r"(addr));
}

__device__ __forceinline__ void mma_16816(float* d, const unsigned* a,
                                          const unsigned* b) {
    asm volatile(
        "mma.sync.aligned.m16n8k16.row.col.f32.f16.f16.f32 "
        "{%0,%1,%2,%3}, {%4,%5,%6,%7}, {%8,%9}, {%0,%1,%2,%3};\n"
        : "+f"(d[0]), "+f"(d[1]), "+f"(d[2]), "+f"(d[3])
        : "r"(a[0]), "r"(a[1]), "r"(a[2]), "r"(a[3]), "r"(b[0]), "r"(b[1]));
}

// ---------------------------------------------------------------------------
__global__ void f32_to_f16_kernel(const float* __restrict__ in,
                                  __half* __restrict__ out, int n2) {
    int i = blockIdx.x * blockDim.x + threadIdx.x;
    if (i < n2) {
        float2 v = ((const float2*)in)[i];
        ((__half2*)out)[i] = __floats2half2_rn(v.x, v.y);
    }
}

// ---------------------------------------------------------------------------
// HMMA GEMM core: C[m][n] = sum_k A[m][k]*B[n][k].
// Tile 128x64, BK=32, 256 threads = 8 warps (4x2), warp tile 32x32.
// cp.async double-buffered staging; ldmatrix.x4 fragment loads.
// Strides padded to 40 halves (80 B): rows r*80 mod 128 cover all 8 distinct
// 16B groups -> conflict-free ldmatrix.
// ---------------------------------------------------------------------------
#define BM 128
#define BN 64
#define BK 32
#define SSTR 40

__device__ __forceinline__ void gemm_ldm_core(
    const __half* __restrict__ A, const __half* __restrict__ B,
    int m0, int n0, int K, float acc[2][4][4],
    __half* As, __half* Bs) {
    const int tid = threadIdx.x;
    const int lane = tid & 31;
    const int w = tid >> 5;
    const int wm = w >> 1, wn = w & 1;

    #pragma unroll
    for (int i = 0; i < 2; i++)
        #pragma unroll
        for (int j = 0; j < 4; j++)
            #pragma unroll
            for (int e = 0; e < 4; e++) acc[i][j][e] = 0.f;

    const __half* Ag = A + (size_t)m0 * K;
    const __half* Bg = B + (size_t)n0 * K;

    const int ar = tid >> 2, ac8 = (tid & 3) * 8;          // A chunk 0 (+256)
    const int br = tid >> 2, bc8 = (tid & 3) * 8;          // B chunk

    // prologue: stage 0
    {
        __half* as = As;
        __half* bs = Bs;
        CP_ASYNC16(smem_u32(&as[ar * SSTR + ac8]), &Ag[(size_t)ar * K + ac8]);
        CP_ASYNC16(smem_u32(&as[(ar + 64) * SSTR + ac8]),
                   &Ag[(size_t)(ar + 64) * K + ac8]);
        CP_ASYNC16(smem_u32(&bs[br * SSTR + bc8]), &Bg[(size_t)br * K + bc8]);
        CP_COMMIT();
    }

    const int NS = K / BK;
    for (int s = 0; s < NS; s++) {
        CP_WAIT0();
        __syncthreads();
        if (s + 1 < NS) {
            const int k0 = (s + 1) * BK;
            __half* as = As + ((s + 1) & 1) * (BM * SSTR);
            __half* bs = Bs + ((s + 1) & 1) * (BN * SSTR);
            CP_ASYNC16(smem_u32(&as[ar * SSTR + ac8]),
                       &Ag[(size_t)ar * K + k0 + ac8]);
            CP_ASYNC16(smem_u32(&as[(ar + 64) * SSTR + ac8]),
                       &Ag[(size_t)(ar + 64) * K + k0 + ac8]);
            CP_ASYNC16(smem_u32(&bs[br * SSTR + bc8]),
                       &Bg[(size_t)br * K + k0 + bc8]);
            CP_COMMIT();
        }

        const __half* as = As + (s & 1) * (BM * SSTR);
        const __half* bs = Bs + (s & 1) * (BN * SSTR);

        #pragma unroll
        for (int kc = 0; kc < 2; kc++) {
            unsigned af[2][4], bf[2][4];
            #pragma unroll
            for (int i = 0; i < 2; i++) {
                unsigned addr = smem_u32(
                    &as[(wm * 32 + i * 16 + (lane & 15)) * SSTR +
                        kc * 16 + (lane >> 4) * 8]);
                ldmatrix_x4(af[i], addr);
            }
            #pragma unroll
            for (int j = 0; j < 2; j++) {
                const int row = wn * 32 + j * 16 + (lane & 7) +
                                ((lane >> 4) & 1) * 8;
                const int col = kc * 16 + ((lane >> 3) & 1) * 8;
                ldmatrix_x4(bf[j], smem_u32(&bs[row * SSTR + col]));
            }
            #pragma unroll
            for (int i = 0; i < 2; i++)
                #pragma unroll
                for (int j = 0; j < 2; j++) {
                    mma_16816(acc[i][2 * j], af[i], &bf[j][0]);
                    mma_16816(acc[i][2 * j + 1], af[i], &bf[j][2]);
                }
        }
    }
}

// ---------------------------------------------------------------------------
// Kernel: QKV GEMM + bias + scatter to q/k (row) and v (transposed)
// ---------------------------------------------------------------------------
__global__ __launch_bounds__(256)
void qkv_gemm_f16(const float* __restrict__ bias) {
    __shared__ __half As[2 * BM * SSTR];
    __shared__ __half Bs[2 * BN * SSTR];
    const int m0 = blockIdx.x * BM;
    const int n0 = blockIdx.y * BN;

    float acc[2][4][4];
    gemm_ldm_core(g_xh, g_wqkvh, m0, n0, EMB, acc, As, Bs);

    const int tid = threadIdx.x;
    const int lane = tid & 31;
    const int w = tid >> 5;
    const int wm = w >> 1, wn = w & 1;
    const int g = lane >> 2, q4 = lane & 3;

    const int which = n0 / EMB;          // 0=q 1=k 2=v, uniform per block
    const int h = (n0 % EMB) / 64;       // uniform per block

    #pragma unroll
    for (int i = 0; i < 2; i++) {
        #pragma unroll
        for (int j = 0; j < 4; j++) {
            const int d = wn * 32 + j * 8 + 2 * q4;     // 0..62 even
            const int n = n0 + d;
            const float b0 = bias[n], b1 = bias[n + 1];
            #pragma unroll
            for (int rr = 0; rr < 2; rr++) {
                const int m = m0 + wm * 32 + i * 16 + g + rr * 8;
                const int bidx = m >> 11;
                const int s = m & 2047;
                const int bh = bidx * NHEAD + h;
                const float v0 = acc[i][j][rr * 2 + 0] + b0;
                const float v1 = acc[i][j][rr * 2 + 1] + b1;
                if (which == 2) {
                    g_vth[((size_t)bh * 64 + d) * SEQ + s] = __float2half(v0);
                    g_vth[((size_t)bh * 64 + d + 1) * SEQ + s] = __float2half(v1);
                } else {
                    __half* dst = (which == 0) ? g_qh : g_kh;
                    *(__half2*)&dst[((size_t)bh * SEQ + s) * 64 + d] =
                        __floats2half2_rn(v0, v1);
                }
            }
        }
    }
}

// ---------------------------------------------------------------------------
// Kernel: proj GEMM + bias -> fp32 out
// ---------------------------------------------------------------------------
__global__ __launch_bounds__(256)
void proj_gemm_f16(const float* __restrict__ bias, float* __restrict__ out) {
    __shared__ __half As[2 * BM * SSTR];
    __shared__ __half Bs[2 * BN * SSTR];
    const int m0 = blockIdx.x * BM;
    const int n0 = blockIdx.y * BN;

    float acc[2][4][4];
    gemm_ldm_core(g_attnh, g_wprojh, m0, n0, EMB, acc, As, Bs);

    const int tid = threadIdx.x;
    const int lane = tid & 31;
    const int w = tid >> 5;
    const int wm = w >> 1, wn = w & 1;
    const int g = lane >> 2, q4 = lane & 3;

    #pragma unroll
    for (int i = 0; i < 2; i++) {
        #pragma unroll
        for (int j = 0; j < 4; j++) {
            const int n = n0 + wn * 32 + j * 8 + 2 * q4;
            const float b0 = bias[n], b1 = bias[n + 1];
            #pragma unroll
            for (int rr = 0; rr < 2; rr++) {
                const int m = m0 + wm * 32 + i * 16 + g + rr * 8;
                float2 v;
                v.x = acc[i][j][rr * 2 + 0] + b0;
                v.y = acc[i][j][rr * 2 + 1] + b1;
                *(float2*)&out[(size_t)m * EMB + n] = v;
            }
        }
    }
}

// ---------------------------------------------------------------------------
// Kernel: flash attention with HMMA + ldmatrix + cp.async double buffering.
// Block = 64 queries (4 warps x 16), KV tiles of 64 keys.
// Smem K [key][d], Vt [d][key], stride 72 halves (conflict-free for ldmatrix).
// ---------------------------------------------------------------------------
#define ASTRIDE 72

__global__ __launch_bounds__(128)
void attn_mma_kernel() {
    const int bh = blockIdx.y;                 // 0..47
    const int b = bh / NHEAD;
    const int h = bh % NHEAD;
    const int tid = threadIdx.x;
    const int lane = tid & 31;
    const int w = tid >> 5;
    const int g = lane >> 2, q4 = lane & 3;
    const int qbase = blockIdx.x * 64 + w * 16;

    __shared__ __half Ks[2][64 * ASTRIDE];
    __shared__ __half Vs[2][64 * ASTRIDE];

    // Q fragments (A-layout) straight from gmem
    unsigned qa[4][4];
    {
        const __half* qp = g_qh + ((size_t)bh * SEQ + qbase) * HDIM;
        #pragma unroll
        for (int c = 0; c < 4; c++) {
            qa[c][0] = *(const unsigned*)&qp[(size_t)(g) * 64 + 16 * c + 2 * q4];
            qa[c][1] = *(const unsigned*)&qp[(size_t)(g + 8) * 64 + 16 * c + 2 * q4];
            qa[c][2] = *(const unsigned*)&qp[(size_t)(g) * 64 + 16 * c + 8 + 2 * q4];
            qa[c][3] = *(const unsigned*)&qp[(size_t)(g + 8) * 64 + 16 * c + 8 + 2 * q4];
        }
    }

    float O[8][4];
    #pragma unroll
    for (int n = 0; n < 8; n++)
        #pragma unroll
        for (int e = 0; e < 4; e++) O[n][e] = 0.f;
    float mA = -1e30f, mB = -1e30f, lA = 0.f, lB = 0.f;

    const __half* kgb = g_kh + (size_t)bh * SEQ * HDIM;
    const __half* vgb = g_vth + (size_t)bh * 64 * SEQ;

    // prologue: stage tile 0
    {
        #pragma unroll
        for (int it = 0; it < 4; it++) {
            int i = tid + it * 128;
            int r = i >> 3, c8 = (i & 7) * 8;
            CP_ASYNC16(smem_u32(&Ks[0][r * ASTRIDE + c8]),
                       &kgb[(size_t)r * 64 + c8]);
            CP_ASYNC16(smem_u32(&Vs[0][r * ASTRIDE + c8]),
                       &vgb[(size_t)r * SEQ + c8]);
        }
        CP_COMMIT();
    }

    for (int t = 0; t < SEQ / 64; t++) {
        CP_WAIT0();
        __syncthreads();
        if (t + 1 < SEQ / 64) {
            const int k0 = (t + 1) * 64;
            const int buf = (t + 1) & 1;
            #pragma unroll
            for (int it = 0; it < 4; it++) {
                int i = tid + it * 128;
                int r = i >> 3, c8 = (i & 7) * 8;
                CP_ASYNC16(smem_u32(&Ks[buf][r * ASTRIDE + c8]),
                           &kgb[(size_t)(t + 1) * 64 * 64 + (size_t)r * 64 + c8]);
                CP_ASYNC16(smem_u32(&Vs[buf][r * ASTRIDE + c8]),
                           &vgb[(size_t)r * SEQ + k0 + c8]);
            }
            CP_COMMIT();
        }

        const __half* ks = Ks[t & 1];
        const __half* vs = Vs[t & 1];

        // scores S = Q K^T * scale (fp32)
        float S[8][4];
        #pragma unroll
        for (int n = 0; n < 8; n++)
            #pragma unroll
            for (int e = 0; e < 4; e++) S[n][e] = 0.f;

        #pragma unroll
        for (int kp = 0; kp < 4; kp++) {      // key16 groups
            unsigned bf[4][4];
            #pragma unroll
            for (int c = 0; c < 4; c++) {     // d16 chunks
                const int row = kp * 16 + (lane & 7) + ((lane >> 4) & 1) * 8;
                const int col = c * 16 + ((lane >> 3) & 1) * 8;
                ldmatrix_x4(bf[c], smem_u32(&ks[row * ASTRIDE + col]));
            }
            #pragma unroll
            for (int c = 0; c < 4; c++) {
                mma_16816(S[2 * kp], qa[c], &bf[c][0]);
                mma_16816(S[2 * kp + 1], qa[c], &bf[c][2]);
            }
        }
        #pragma unroll
        for (int n = 0; n < 8; n++)
            #pragma unroll
            for (int e = 0; e < 4; e++) S[n][e] *= 0.125f;

        // online softmax (rows g and g+8 per thread; quads share a row)
        float tmA = -1e30f, tmB = -1e30f;
        #pragma unroll
        for (int n = 0; n < 8; n++) {
            tmA = fmaxf(tmA, fmaxf(S[n][0], S[n][1]));
            tmB = fmaxf(tmB, fmaxf(S[n][2], S[n][3]));
        }
        tmA = fmaxf(tmA, __shfl_xor_sync(0xffffffffu, tmA, 1));
        tmA = fmaxf(tmA, __shfl_xor_sync(0xffffffffu, tmA, 2));
        tmB = fmaxf(tmB, __shfl_xor_sync(0xffffffffu, tmB, 1));
        tmB = fmaxf(tmB, __shfl_xor_sync(0xffffffffu, tmB, 2));

        const float nmA = fmaxf(mA, tmA), nmB = fmaxf(mB, tmB);
        const float efA = __expf(mA - nmA), efB = __expf(mB - nmB);

        float sA = 0.f, sB = 0.f;
        #pragma unroll
        for (int n = 0; n < 8; n++) {
            S[n][0] = __expf(S[n][0] - nmA);
            S[n][1] = __expf(S[n][1] - nmA);
            S[n][2] = __expf(S[n][2] - nmB);
            S[n][3] = __expf(S[n][3] - nmB);
            sA += S[n][0] + S[n][1];
            sB += S[n][2] + S[n][3];
        }
        sA += __shfl_xor_sync(0xffffffffu, sA, 1);
        sA += __shfl_xor_sync(0xffffffffu, sA, 2);
        sB += __shfl_xor_sync(0xffffffffu, sB, 1);
        sB += __shfl_xor_sync(0xffffffffu, sB, 2);

        lA = lA * efA + sA;
        lB = lB * efB + sB;
        mA = nmA;
        mB = nmB;
        #pragma unroll
        for (int n = 0; n < 8; n++) {
            O[n][0] *= efA; O[n][1] *= efA;
            O[n][2] *= efB; O[n][3] *= efB;
        }

        // pack P (C-frag pairs -> A-frags)
        unsigned pa[4][4];
        #pragma unroll
        for (int c = 0; c < 4; c++) {
            pa[c][0] = pack2(S[2 * c][0], S[2 * c][1]);
            pa[c][1] = pack2(S[2 * c][2], S[2 * c][3]);
            pa[c][2] = pack2(S[2 * c + 1][0], S[2 * c + 1][1]);
            pa[c][3] = pack2(S[2 * c + 1][2], S[2 * c + 1][3]);
        }

        // O += P @ V   (B = Vt[d][key])
        #pragma unroll
        for (int dp = 0; dp < 4; dp++) {      // d16 groups
            unsigned bf[4][4];
            #pragma unroll
            for (int c = 0; c < 4; c++) {     // key16 chunks
                const int row = dp * 16 + (lane & 7) + ((lane >> 4) & 1) * 8;
                const int col = c * 16 + ((lane >> 3) & 1) * 8;
                ldmatrix_x4(bf[c], smem_u32(&vs[row * ASTRIDE + col]));
            }
            #pragma unroll
            for (int c = 0; c < 4; c++) {
                mma_16816(O[2 * dp], pa[c], &bf[c][0]);
                mma_16816(O[2 * dp + 1], pa[c], &bf[c][2]);
            }
        }
    }

    // epilogue: normalize + store to g_attnh [b*s][h*64+d]
    const float rA = 1.f / lA, rB = 1.f / lB;
    #pragma unroll
    for (int n = 0; n < 8; n++) {
        const int d = n * 8 + 2 * q4;
        {
            const int q = qbase + g;
            *(__half2*)&g_attnh[((size_t)(b * SEQ + q)) * EMB + h * 64 + d] =
                __floats2half2_rn(O[n][0] * rA, O[n][1] * rA);
        }
        {
            const int q = qbase + g + 8;
            *(__half2*)&g_attnh[((size_t)(b * SEQ + q)) * EMB + h * 64 + d] =
                __floats2half2_rn(O[n][2] * rB, O[n][3] * rB);
        }
    }
}

// ---------------------------------------------------------------------------
extern "C" void kernel_launch(void* const* d_in, const int* in_sizes, int n_in,
                              void* d_out, int out_size) {
    const float* x      = (const float*)d_in[0];   // [4,2048,768]
    const float* w_qkv  = (const float*)d_in[1];   // [2304,768]
    const float* b_qkv  = (const float*)d_in[2];   // [2304]
    const float* w_proj = (const float*)d_in[3];   // [768,768]
    const float* b_proj = (const float*)d_in[4];   // [768]
    float* out = (float*)d_out;                    // [4,2048,768]

    __half* p_xh;     cudaGetSymbolAddress((void**)&p_xh, g_xh);
    __half* p_wqkvh;  cudaGetSymbolAddress((void**)&p_wqkvh, g_wqkvh);
    __half* p_wprojh; cudaGetSymbolAddress((void**)&p_wprojh, g_wprojh);

    {
        int n2 = MROWS * EMB / 2;
        f32_to_f16_kernel<<<(n2 + 255) / 256, 256>>>(x, p_xh, n2);
        n2 = NQKV * EMB / 2;
        f32_to_f16_kernel<<<(n2 + 255) / 256, 256>>>(w_qkv, p_wqkvh, n2);
        n2 = EMB * EMB / 2;
        f32_to_f16_kernel<<<(n2 + 255) / 256, 256>>>(w_proj, p_wprojh, n2);
    }
    {
        dim3 grid(MROWS / BM, NQKV / BN);          // 64 x 36
        qkv_gemm_f16<<<grid, 256>>>(b_qkv);
    }
    {
        dim3 grid(SEQ / 64, BATCH * NHEAD);        // 32 x 48
        attn_mma_kernel<<<grid, 128>>>();
    }
    {
        dim3 grid(MROWS / BM, EMB / BN);           // 64 x 12
        proj_gemm_f16<<<grid, 256>>>(b_proj, out);
    }
}